// round 9
// baseline (speedup 1.0000x reference)
#include <cuda_runtime.h>
#include <cstdint>

#define N_ROWS 131072
#define K_CODES 4096
#define DIM 64
#define MT 128            // rows per CTA
#define NC 128            // codes per chunk
#define NCH (K_CODES/NC)  // 32
#define CAP 128           // candidate slots per row
#define QCAP 16           // per writer (8 writers/row)
#define NW 8

// ---------------- device scratch (no allocation allowed) ----------------
__device__ float          g_zz[N_ROWS];
__device__ float          g_ee[K_CODES];
__device__ int            g_idx[N_ROWS];
__device__ double         g_loss;
__device__ unsigned       g_amaxz_b, g_amaxe_b, g_L1z_b, g_L1e_b;  // float bits, monotone
__device__ float          g_qz, g_qe;     // quantization scales (127/amax)
__device__ int            g_Mint;         // sound margin in integer score units
__device__ __align__(16) signed char g_z8[(size_t)N_ROWS * DIM];
__device__ __align__(16) signed char g_e8[(size_t)K_CODES * DIM];
__device__ int            g_cand[(size_t)N_ROWS * CAP];
__device__ int            g_cnt[(size_t)N_ROWS * NW];

// ---------------- PTX helpers ----------------
#define MMA_S8(c, a, b0, b1) \
    asm volatile("mma.sync.aligned.m16n8k32.row.col.s32.s8.s8.s32 " \
        "{%0,%1,%2,%3}, {%4,%5,%6,%7}, {%8,%9}, {%0,%1,%2,%3};" \
        : "+r"((c)[0]), "+r"((c)[1]), "+r"((c)[2]), "+r"((c)[3]) \
        : "r"((a)[0]), "r"((a)[1]), "r"((a)[2]), "r"((a)[3]), "r"(b0), "r"(b1))

#define CP_ASYNC16(sa, gp) \
    asm volatile("cp.async.cg.shared.global [%0], [%1], 16;" :: "r"((uint32_t)(sa)), "l"(gp) : "memory")
#define CP_COMMIT()  asm volatile("cp.async.commit_group;" ::: "memory")
#define CP_WAITG(n)  asm volatile("cp.async.wait_group %0;" :: "n"(n) : "memory")

__device__ __forceinline__ uint32_t smem_u32(const void* p) {
    uint32_t a;
    asm("{ .reg .u64 t; cvta.to.shared.u64 t, %1; cvt.u32.u64 %0, t; }" : "=r"(a) : "l"(p));
    return a;
}
// 64B rows, 4x16B slots, slot XOR (row>>1)&3 -> conflict-free frag loads
__device__ __forceinline__ uint32_t sw_addr(uint32_t base, int row, int slot, int m4) {
    return base + (uint32_t)row * 64u + (uint32_t)((slot ^ ((row >> 1) & 3)) << 4) + (uint32_t)m4;
}

// ---------------------------------------------------------------------------
// prep1: warp per row. zz/ee (fp32 via double) + amax/L1 reductions.
// atomicMax on positive-float bits is monotone -> replay-idempotent.
// ---------------------------------------------------------------------------
__global__ void vq_prep1(const float* __restrict__ z, const float* __restrict__ emb) {
    int wid = threadIdx.x >> 5, lane = threadIdx.x & 31;
    int r = blockIdx.x * 8 + wid;
    if (blockIdx.x == 0 && threadIdx.x == 0) g_loss = 0.0;
    if (r >= N_ROWS + K_CODES) return;
    const float* src = (r < N_ROWS) ? z + (size_t)r * DIM
                                    : emb + (size_t)(r - N_ROWS) * DIM;
    float2 v = ((const float2*)src)[lane];
    double s = (double)__fmul_rn(v.x, v.x) + (double)__fmul_rn(v.y, v.y);
    float l1 = fabsf(v.x) + fabsf(v.y);
    float am = fmaxf(fabsf(v.x), fabsf(v.y));
    #pragma unroll
    for (int off = 16; off; off >>= 1) {
        s  += __shfl_down_sync(0xffffffffu, s, off);
        l1 += __shfl_down_sync(0xffffffffu, l1, off);
        am  = fmaxf(am, __shfl_down_sync(0xffffffffu, am, off));
    }
    if (lane == 0) {
        if (r < N_ROWS) {
            g_zz[r] = (float)s;
            atomicMax(&g_amaxz_b, __float_as_uint(am));
            atomicMax(&g_L1z_b,   __float_as_uint(l1));
        } else {
            g_ee[r - N_ROWS] = (float)s;
            atomicMax(&g_amaxe_b, __float_as_uint(am));
            atomicMax(&g_L1e_b,   __float_as_uint(l1));
        }
    }
}

// scale + sound integer margin (single thread)
__global__ void vq_scale() {
    float amz = __uint_as_float(g_amaxz_b);
    float ame = __uint_as_float(g_amaxe_b);
    double L1z = (double)__uint_as_float(g_L1z_b);
    double L1e = (double)__uint_as_float(g_L1e_b);
    double qz = 127.0 / (double)amz;
    double qe = 127.0 / (double)ame;
    double dz = 0.5000005 / qz;            // value-unit quantization bounds
    double de = 0.5000005 / qe;
    double ds = dz * L1e + L1z * de + 64.0 * dz * de;
    double Ms = 2.0 * ds * 1.02 + 1e-5;    // 2x (two dots) + d-grid pad + slack
    g_qz = (float)qz;
    g_qe = (float)qe;
    g_Mint = (int)ceil(Ms * qz * qe) + 1;
}

// prep2: quantize z/emb to int8 (round-to-nearest; |v*q| <= 127 by construction)
__global__ void vq_prep2(const float* __restrict__ z, const float* __restrict__ emb) {
    const long long nz = (long long)N_ROWS * DIM / 4;
    const long long ne = (long long)K_CODES * DIM / 4;
    long long t = (long long)blockIdx.x * blockDim.x + threadIdx.x;
    if (t >= nz + ne) return;
    float q; const float4* src; char4* dst;
    if (t < nz) { q = g_qz; src = (const float4*)z + t;   dst = (char4*)g_z8 + t; }
    else        { q = g_qe; src = (const float4*)emb + (t - nz); dst = (char4*)g_e8 + (t - nz); }
    float4 v = *src;
    char4 c;
    c.x = (signed char)__float2int_rn(v.x * q);
    c.y = (signed char)__float2int_rn(v.y * q);
    c.z = (signed char)__float2int_rn(v.z * q);
    c.w = (signed char)__float2int_rn(v.w * q);
    *dst = c;
}

// ---------------------------------------------------------------------------
// pass 1: int8 IMMA m16n8k32 (exact s32 accum), 512 threads, warp grid
// 8(m)x2(n), warp tile 16 rows x 64 codes, 2 IMMA per 16x8 tile (k=64).
// Frag loads are plain LDS.32 from slot-swizzled 64B-row smem (conflict-free).
// Integer epilogue: imax tree + quad shfl + fixed-threshold collection.
// ---------------------------------------------------------------------------
extern __shared__ char sm_dyn[];

__global__ void __launch_bounds__(512)
vq_pass1() {
    const int tid = threadIdx.x;
    const int lane = tid & 31;
    const int wid = tid >> 5;
    const int warp_m = wid & 7;
    const int warp_n = wid >> 3;
    const int g = lane >> 2;
    const int m = lane & 3;
    const int rowBase = blockIdx.x * MT;

    char* base = (char*)(((uintptr_t)sm_dyn + 127) & ~(uintptr_t)127);
    uint32_t uZ = smem_u32(base);          // Z: 128 x 64B = 8KB
    uint32_t uE = uZ + MT * 64;            // E: 2 x (128 x 64B) = 16KB

    // prologue: Z (512 segs), E0, E1 (512 segs each); swizzled stores
    {
        const char* zsrc = (const char*)g_z8 + (size_t)rowBase * 64;
        CP_ASYNC16(sw_addr(uZ, tid >> 2, tid & 3, 0), zsrc + (uint32_t)tid * 16);
        const char* e0 = (const char*)g_e8;
        CP_ASYNC16(sw_addr(uE, tid >> 2, tid & 3, 0), e0 + (uint32_t)tid * 16);
        CP_COMMIT();
        const char* e1 = (const char*)g_e8 + NC * 64;
        CP_ASYNC16(sw_addr(uE + 8192, tid >> 2, tid & 3, 0), e1 + (uint32_t)tid * 16);
        CP_COMMIT();
    }
    CP_WAITG(1);
    __syncthreads();

    // A fragments: resident. kc=0 -> slots 0,1 ; kc=1 -> slots 2,3
    int afr[2][4];
    {
        const int rlo = warp_m * 16 + g, rhi = rlo + 8;
        #pragma unroll
        for (int kc = 0; kc < 2; kc++) {
            afr[kc][0] = *(const int*)(base + (sw_addr(uZ, rlo, kc * 2,     m * 4) - uZ));
            afr[kc][1] = *(const int*)(base + (sw_addr(uZ, rhi, kc * 2,     m * 4) - uZ));
            afr[kc][2] = *(const int*)(base + (sw_addr(uZ, rlo, kc * 2 + 1, m * 4) - uZ));
            afr[kc][3] = *(const int*)(base + (sw_addr(uZ, rhi, kc * 2 + 1, m * 4) - uZ));
        }
    }

    const int Mint = g_Mint;
    const int w = warp_n * 4 + m;
    const int r0 = rowBase + warp_m * 16 + g;
    int rmax[2] = {-(1 << 29), -(1 << 29)};
    int cnt[2] = {0, 0};
    int* sp[2];
    sp[0] = g_cand + (size_t)r0 * CAP + w * QCAP;
    sp[1] = g_cand + (size_t)(r0 + 8) * CAP + w * QCAP;

    for (int c = 0; c < NCH; c++) {
        if (c) { CP_WAITG(1); __syncthreads(); }
        char* ebuf = base + (MT * 64) + (c & 1) * 8192;
        uint32_t eb = uE + (uint32_t)((c & 1) * 8192);

        int acc[8][4];
        #pragma unroll
        for (int nt = 0; nt < 8; nt++)
            #pragma unroll
            for (int q = 0; q < 4; q++) acc[nt][q] = 0;

        #pragma unroll
        for (int nt = 0; nt < 8; nt++) {
            const int code = warp_n * 64 + nt * 8 + g;
            int b0 = *(const int*)(ebuf + (sw_addr(eb, code, 0, m * 4) - eb));
            int b1 = *(const int*)(ebuf + (sw_addr(eb, code, 1, m * 4) - eb));
            int b2 = *(const int*)(ebuf + (sw_addr(eb, code, 2, m * 4) - eb));
            int b3 = *(const int*)(ebuf + (sw_addr(eb, code, 3, m * 4) - eb));
            MMA_S8(acc[nt], afr[0], b0, b1);
            MMA_S8(acc[nt], afr[1], b2, b3);
        }

        __syncthreads();                      // all warps done reading E[c&1]
        if (c + 2 < NCH) {                    // prefetch E[c+2] into buf c&1
            const char* en = (const char*)g_e8 + (size_t)(c + 2) * (NC * 64);
            uint32_t sb = uE + (uint32_t)((c & 1) * 8192);
            CP_ASYNC16(sw_addr(sb, tid >> 2, tid & 3, 0), en + (uint32_t)tid * 16);
        }
        CP_COMMIT();                          // uniform group counts

        // ---- phase 1: integer max tree + quad share ----
        int cm0 = acc[0][0] > acc[0][1] ? acc[0][0] : acc[0][1];
        int cm1 = acc[0][2] > acc[0][3] ? acc[0][2] : acc[0][3];
        #pragma unroll
        for (int nt = 1; nt < 8; nt++) {
            int a0 = acc[nt][0] > acc[nt][1] ? acc[nt][0] : acc[nt][1];
            int a1 = acc[nt][2] > acc[nt][3] ? acc[nt][2] : acc[nt][3];
            cm0 = cm0 > a0 ? cm0 : a0;
            cm1 = cm1 > a1 ? cm1 : a1;
        }
        #pragma unroll
        for (int off = 1; off <= 2; off <<= 1) {
            int o0 = __shfl_xor_sync(0xffffffffu, cm0, off);
            int o1 = __shfl_xor_sync(0xffffffffu, cm1, off);
            cm0 = cm0 > o0 ? cm0 : o0;
            cm1 = cm1 > o1 ? cm1 : o1;
        }
        rmax[0] = rmax[0] > cm0 ? rmax[0] : cm0;
        rmax[1] = rmax[1] > cm1 ? rmax[1] : cm1;
        const int thr0 = rmax[0] - Mint;
        const int thr1 = rmax[1] - Mint;

        // ---- phase 2: independent predicated collection ----
        #pragma unroll
        for (int nt = 0; nt < 8; nt++) {
            const int colb = c * NC + warp_n * 64 + nt * 8 + m * 2;
            if (acc[nt][0] > thr0) { if (cnt[0] < QCAP) sp[0][cnt[0]] = colb;     cnt[0]++; }
            if (acc[nt][1] > thr0) { if (cnt[0] < QCAP) sp[0][cnt[0]] = colb + 1; cnt[0]++; }
            if (acc[nt][2] > thr1) { if (cnt[1] < QCAP) sp[1][cnt[1]] = colb;     cnt[1]++; }
            if (acc[nt][3] > thr1) { if (cnt[1] < QCAP) sp[1][cnt[1]] = colb + 1; cnt[1]++; }
        }
    }

    g_cnt[(size_t)r0 * NW + w] = cnt[0];       // raw (overflow visible)
    g_cnt[(size_t)(r0 + 8) * NW + w] = cnt[1];
}

// ---------------------------------------------------------------------------
// rescore: warp per row; slot-mask iteration, exact serial-FMA distance
// (bit-identical to R1, which matched exactly). Overflow -> full scan.
// ---------------------------------------------------------------------------
__global__ void __launch_bounds__(256)
vq_rescore(const float* __restrict__ z, const float* __restrict__ emb) {
    __shared__ float zs[8][DIM];
    const int wid = threadIdx.x >> 5, lane = threadIdx.x & 31;
    const int row = blockIdx.x * 8 + wid;

    float2 v = ((const float2*)(z + (size_t)row * DIM))[lane];
    zs[wid][2 * lane] = v.x;
    zs[wid][2 * lane + 1] = v.y;
    __syncwarp();

    int myc = (lane < NW) ? g_cnt[(size_t)row * NW + lane] : 0;
    bool ovf = __any_sync(0xffffffffu, myc > QCAP);

    const float zzr = g_zz[row];
    const int* cbase = g_cand + (size_t)row * CAP;
    float best = __int_as_float(0x7f800000);
    int bidx = 0x7fffffff;

    if (!ovf) {
        #pragma unroll
        for (int it = 0; it < 4; it++) {
            int slot = lane + it * 32;
            int sw = slot >> 4;
            int j  = slot & 15;
            int cw = __shfl_sync(0xffffffffu, myc, sw);
            if (j < cw) {
                int cand = cbase[slot];
                const float4* e4 = (const float4*)(emb + (size_t)cand * DIM);
                float s = 0.0f;
                #pragma unroll
                for (int q = 0; q < 16; q++) {
                    float4 e = __ldg(e4 + q);
                    s = __fmaf_rn(zs[wid][4 * q + 0], e.x, s);
                    s = __fmaf_rn(zs[wid][4 * q + 1], e.y, s);
                    s = __fmaf_rn(zs[wid][4 * q + 2], e.z, s);
                    s = __fmaf_rn(zs[wid][4 * q + 3], e.w, s);
                }
                float t = __fadd_rn(zzr, g_ee[cand]);
                float d = __fmaf_rn(-2.0f, s, t);
                if (d < best || (d == best && cand < bidx)) { best = d; bidx = cand; }
            }
        }
    } else {
        for (int cand = lane; cand < K_CODES; cand += 32) {
            const float4* e4 = (const float4*)(emb + (size_t)cand * DIM);
            float s = 0.0f;
            #pragma unroll
            for (int q = 0; q < 16; q++) {
                float4 e = __ldg(e4 + q);
                s = __fmaf_rn(zs[wid][4 * q + 0], e.x, s);
                s = __fmaf_rn(zs[wid][4 * q + 1], e.y, s);
                s = __fmaf_rn(zs[wid][4 * q + 2], e.z, s);
                s = __fmaf_rn(zs[wid][4 * q + 3], e.w, s);
            }
            float t = __fadd_rn(zzr, g_ee[cand]);
            float d = __fmaf_rn(-2.0f, s, t);
            if (d < best || (d == best && cand < bidx)) { best = d; bidx = cand; }
        }
    }
    #pragma unroll
    for (int off = 16; off >= 1; off >>= 1) {
        float od = __shfl_xor_sync(0xffffffffu, best, off);
        int   oi = __shfl_xor_sync(0xffffffffu, bidx, off);
        if (od < best || (od == best && oi < bidx)) { best = od; bidx = oi; }
    }
    if (lane == 0) g_idx[row] = (bidx == 0x7fffffff) ? 0 : bidx;
}

// ---------------------------------------------------------------------------
// output + loss: float4-vectorized, same rounding as R1.
// ---------------------------------------------------------------------------
__global__ void vq_output(const float* __restrict__ z, const float* __restrict__ emb,
                          float* __restrict__ out, long long outSize) {
    long long t  = (long long)blockIdx.x * blockDim.x + threadIdx.x;
    long long nd = (long long)N_ROWS * DIM;
    long long nseg = nd >> 2;
    double sq = 0.0;
    if (t < nseg) {
        int row = (int)(t >> 4);
        int seg = (int)(t & 15);
        int idx = g_idx[row];
        float4 e  = __ldg((const float4*)(emb + (size_t)idx * DIM) + seg);
        float4 zv = ((const float4*)z)[t];
        float dx = __fsub_rn(e.x, zv.x), dy = __fsub_rn(e.y, zv.y);
        float dz = __fsub_rn(e.z, zv.z), dw = __fsub_rn(e.w, zv.w);
        if (t * 4 + 3 < outSize) {
            float4 o;
            o.x = __fadd_rn(zv.x, dx); o.y = __fadd_rn(zv.y, dy);
            o.z = __fadd_rn(zv.z, dz); o.w = __fadd_rn(zv.w, dw);
            ((float4*)out)[t] = o;
        }
        sq = (double)__fmul_rn(dx, dx) + (double)__fmul_rn(dy, dy)
           + (double)__fmul_rn(dz, dz) + (double)__fmul_rn(dw, dw);
        if (t < N_ROWS && nd + t < outSize) out[nd + t] = (float)g_idx[(int)t];
    }
    #pragma unroll
    for (int off = 16; off >= 1; off >>= 1) sq += __shfl_down_sync(0xffffffffu, sq, off);
    __shared__ double wsum[8];
    int lane = threadIdx.x & 31, wid = threadIdx.x >> 5;
    if (lane == 0) wsum[wid] = sq;
    __syncthreads();
    if (threadIdx.x == 0) {
        double b = 0.0;
        #pragma unroll
        for (int w = 0; w < 8; w++) b += wsum[w];
        atomicAdd(&g_loss, b);
    }
}

__global__ void vq_finalize(float* __restrict__ out, long long outSize) {
    long long nd = (long long)N_ROWS * DIM;
    if (nd + N_ROWS < outSize) {
        float mf = (float)(g_loss / (double)nd);
        out[nd + N_ROWS] = __fmaf_rn(0.5f, mf, mf);
    }
}

// ---------------------------------------------------------------------------
extern "C" void kernel_launch(void* const* d_in, const int* in_sizes, int n_in,
                              void* d_out, int out_size) {
    const float* z   = (const float*)d_in[0];
    const float* emb = (const float*)d_in[1];
    float* out = (float*)d_out;

    const int dynSmem = 128 + MT * 64 + 2 * (NC * 64);  // ~24.7 KB
    cudaFuncSetAttribute(vq_pass1, cudaFuncAttributeMaxDynamicSharedMemorySize, dynSmem);

    vq_prep1<<<(N_ROWS + K_CODES) / 8, 256>>>(z, emb);
    vq_scale<<<1, 1>>>();
    long long nq = ((long long)(N_ROWS + K_CODES) * DIM) / 4;
    vq_prep2<<<(int)((nq + 255) / 256), 256>>>(z, emb);
    vq_pass1<<<N_ROWS / MT, 512, dynSmem>>>();
    vq_rescore<<<N_ROWS / 8, 256>>>(z, emb);
    long long nd = (long long)N_ROWS * DIM;
    long long nseg = nd >> 2;
    vq_output<<<(int)((nseg + 255) / 256), 256>>>(z, emb, out, (long long)out_size);
    vq_finalize<<<1, 1>>>(out, (long long)out_size);
}

// round 11
// speedup vs baseline: 1.3968x; 1.3968x over previous
#include <cuda_runtime.h>
#include <cstdint>

#define N_ROWS 131072
#define K_CODES 4096
#define DIM 64
#define MT 128            // rows per CTA
#define NC 128            // codes per chunk
#define NCH (K_CODES/NC)  // 32
#define QCAP 20           // per writer (8 writers/row)
#define CAP (8*QCAP)      // 160 candidate slots per row
#define NW 8

// ---------------- device scratch (no allocation allowed) ----------------
__device__ float          g_zz[N_ROWS];
__device__ float          g_ee[K_CODES];
__device__ int            g_idx[N_ROWS];
__device__ double         g_loss;
__device__ unsigned       g_amaxz_b, g_amaxe_b, g_L1z_b, g_L1e_b;  // float bits, monotone
__device__ float          g_qz, g_qe;     // quantization scales (127/amax)
__device__ int            g_Mint;         // sound margin in integer score units
__device__ __align__(16) signed char g_z8[(size_t)N_ROWS * DIM];
__device__ __align__(16) signed char g_e8[(size_t)K_CODES * DIM];
__device__ int            g_cand[(size_t)N_ROWS * CAP];
__device__ int            g_cnt[(size_t)N_ROWS * NW];

// ---------------- PTX helpers ----------------
#define MMA_S8(c, a, b0, b1) \
    asm volatile("mma.sync.aligned.m16n8k32.row.col.s32.s8.s8.s32 " \
        "{%0,%1,%2,%3}, {%4,%5,%6,%7}, {%8,%9}, {%0,%1,%2,%3};" \
        : "+r"((c)[0]), "+r"((c)[1]), "+r"((c)[2]), "+r"((c)[3]) \
        : "r"((a)[0]), "r"((a)[1]), "r"((a)[2]), "r"((a)[3]), "r"(b0), "r"(b1))

#define CP_ASYNC16(sa, gp) \
    asm volatile("cp.async.cg.shared.global [%0], [%1], 16;" :: "r"((uint32_t)(sa)), "l"(gp) : "memory")
#define CP_COMMIT()  asm volatile("cp.async.commit_group;" ::: "memory")
#define CP_WAITG(n)  asm volatile("cp.async.wait_group %0;" :: "n"(n) : "memory")

__device__ __forceinline__ uint32_t smem_u32(const void* p) {
    uint32_t a;
    asm("{ .reg .u64 t; cvta.to.shared.u64 t, %1; cvt.u32.u64 %0, t; }" : "=r"(a) : "l"(p));
    return a;
}
// 64B rows, 4x16B slots, slot XOR (row>>1)&3 -> conflict-free frag loads
__device__ __forceinline__ uint32_t sw_addr(uint32_t base, int row, int slot, int m4) {
    return base + (uint32_t)row * 64u + (uint32_t)((slot ^ ((row >> 1) & 3)) << 4) + (uint32_t)m4;
}

// ---------------------------------------------------------------------------
// prep1: warp per row (zz/ee via double) + HIERARCHICAL amax/L1 reduction:
// warp -> smem -> ONE atomic per block per quantity (blocks homogeneous z/e:
// z-rows span exactly blocks [0, N_ROWS/8)). ~17k atomics total vs 1M in R9.
// ---------------------------------------------------------------------------
__global__ void vq_prep1(const float* __restrict__ z, const float* __restrict__ emb) {
    __shared__ float s_am[8], s_l1[8];
    int wid = threadIdx.x >> 5, lane = threadIdx.x & 31;
    int r = blockIdx.x * 8 + wid;
    if (blockIdx.x == 0 && threadIdx.x == 0) g_loss = 0.0;
    bool isZ = (r < N_ROWS);
    const float* src = isZ ? z + (size_t)r * DIM
                           : emb + (size_t)(r - N_ROWS) * DIM;
    float2 v = ((const float2*)src)[lane];
    double s = (double)__fmul_rn(v.x, v.x) + (double)__fmul_rn(v.y, v.y);
    float l1 = fabsf(v.x) + fabsf(v.y);
    float am = fmaxf(fabsf(v.x), fabsf(v.y));
    #pragma unroll
    for (int off = 16; off; off >>= 1) {
        s  += __shfl_down_sync(0xffffffffu, s, off);
        l1 += __shfl_down_sync(0xffffffffu, l1, off);
        am  = fmaxf(am, __shfl_down_sync(0xffffffffu, am, off));
    }
    if (lane == 0) {
        if (isZ) g_zz[r] = (float)s; else g_ee[r - N_ROWS] = (float)s;
        s_am[wid] = am;
        s_l1[wid] = l1;
    }
    __syncthreads();
    if (threadIdx.x == 0) {
        float bam = s_am[0], bl1 = s_l1[0];
        #pragma unroll
        for (int i = 1; i < 8; i++) {
            bam = fmaxf(bam, s_am[i]);
            bl1 = fmaxf(bl1, s_l1[i]);
        }
        if (isZ) {
            atomicMax(&g_amaxz_b, __float_as_uint(bam));
            atomicMax(&g_L1z_b,   __float_as_uint(bl1));
        } else {
            atomicMax(&g_amaxe_b, __float_as_uint(bam));
            atomicMax(&g_L1e_b,   __float_as_uint(bl1));
        }
    }
}

// scale + sound integer margin (single thread)
__global__ void vq_scale() {
    float amz = __uint_as_float(g_amaxz_b);
    float ame = __uint_as_float(g_amaxe_b);
    double L1z = (double)__uint_as_float(g_L1z_b);
    double L1e = (double)__uint_as_float(g_L1e_b);
    double qz = 127.0 / (double)amz;
    double qe = 127.0 / (double)ame;
    double dz = 0.5000005 / qz;            // value-unit quantization bounds
    double de = 0.5000005 / qe;
    double ds = dz * L1e + L1z * de + 64.0 * dz * de;
    double Ms = 2.0 * ds * 1.02 + 1e-5;    // 2x (two dots) + d-grid pad + slack
    g_qz = (float)qz;
    g_qe = (float)qe;
    g_Mint = (int)ceil(Ms * qz * qe) + 1;
}

// prep2: quantize z/emb to int8 (round-to-nearest; |v*q| <= 127 by construction)
__global__ void vq_prep2(const float* __restrict__ z, const float* __restrict__ emb) {
    const long long nz = (long long)N_ROWS * DIM / 4;
    const long long ne = (long long)K_CODES * DIM / 4;
    long long t = (long long)blockIdx.x * blockDim.x + threadIdx.x;
    if (t >= nz + ne) return;
    float q; const float4* src; char4* dst;
    if (t < nz) { q = g_qz; src = (const float4*)z + t;   dst = (char4*)g_z8 + t; }
    else        { q = g_qe; src = (const float4*)emb + (t - nz); dst = (char4*)g_e8 + (t - nz); }
    float4 v = *src;
    char4 c;
    c.x = (signed char)__float2int_rn(v.x * q);
    c.y = (signed char)__float2int_rn(v.y * q);
    c.z = (signed char)__float2int_rn(v.z * q);
    c.w = (signed char)__float2int_rn(v.w * q);
    *dst = c;
}

// ---------------------------------------------------------------------------
// pass 1: int8 IMMA m16n8k32 (exact s32 accum), 512 threads, 2 CTAs/SM,
// warp grid 8(m)x2(n), warp tile 16 rows x 64 codes. Integer epilogue.
// ---------------------------------------------------------------------------
extern __shared__ char sm_dyn[];

__global__ void __launch_bounds__(512, 2)
vq_pass1() {
    const int tid = threadIdx.x;
    const int lane = tid & 31;
    const int wid = tid >> 5;
    const int warp_m = wid & 7;
    const int warp_n = wid >> 3;
    const int g = lane >> 2;
    const int m = lane & 3;
    const int rowBase = blockIdx.x * MT;

    char* base = (char*)(((uintptr_t)sm_dyn + 127) & ~(uintptr_t)127);
    uint32_t uZ = smem_u32(base);          // Z: 128 x 64B = 8KB
    uint32_t uE = uZ + MT * 64;            // E: 2 x (128 x 64B) = 16KB

    // prologue: Z (512 segs), E0, E1 (512 segs each); swizzled stores
    {
        const char* zsrc = (const char*)g_z8 + (size_t)rowBase * 64;
        CP_ASYNC16(sw_addr(uZ, tid >> 2, tid & 3, 0), zsrc + (uint32_t)tid * 16);
        const char* e0 = (const char*)g_e8;
        CP_ASYNC16(sw_addr(uE, tid >> 2, tid & 3, 0), e0 + (uint32_t)tid * 16);
        CP_COMMIT();
        const char* e1 = (const char*)g_e8 + NC * 64;
        CP_ASYNC16(sw_addr(uE + 8192, tid >> 2, tid & 3, 0), e1 + (uint32_t)tid * 16);
        CP_COMMIT();
    }
    CP_WAITG(1);
    __syncthreads();

    // A fragments: resident. kc=0 -> slots 0,1 ; kc=1 -> slots 2,3
    int afr[2][4];
    {
        const int rlo = warp_m * 16 + g, rhi = rlo + 8;
        #pragma unroll
        for (int kc = 0; kc < 2; kc++) {
            afr[kc][0] = *(const int*)(base + (sw_addr(uZ, rlo, kc * 2,     m * 4) - uZ));
            afr[kc][1] = *(const int*)(base + (sw_addr(uZ, rhi, kc * 2,     m * 4) - uZ));
            afr[kc][2] = *(const int*)(base + (sw_addr(uZ, rlo, kc * 2 + 1, m * 4) - uZ));
            afr[kc][3] = *(const int*)(base + (sw_addr(uZ, rhi, kc * 2 + 1, m * 4) - uZ));
        }
    }

    const int Mint = g_Mint;
    const int w = warp_n * 4 + m;
    const int r0 = rowBase + warp_m * 16 + g;
    int rmax[2] = {-(1 << 29), -(1 << 29)};
    int cnt[2] = {0, 0};
    int* sp[2];
    sp[0] = g_cand + (size_t)r0 * CAP + w * QCAP;
    sp[1] = g_cand + (size_t)(r0 + 8) * CAP + w * QCAP;

    for (int c = 0; c < NCH; c++) {
        if (c) { CP_WAITG(1); __syncthreads(); }
        char* ebuf = base + (MT * 64) + (c & 1) * 8192;
        uint32_t eb = uE + (uint32_t)((c & 1) * 8192);

        int acc[8][4];
        #pragma unroll
        for (int nt = 0; nt < 8; nt++)
            #pragma unroll
            for (int q = 0; q < 4; q++) acc[nt][q] = 0;

        #pragma unroll
        for (int nt = 0; nt < 8; nt++) {
            const int code = warp_n * 64 + nt * 8 + g;
            int b0 = *(const int*)(ebuf + (sw_addr(eb, code, 0, m * 4) - eb));
            int b1 = *(const int*)(ebuf + (sw_addr(eb, code, 1, m * 4) - eb));
            int b2 = *(const int*)(ebuf + (sw_addr(eb, code, 2, m * 4) - eb));
            int b3 = *(const int*)(ebuf + (sw_addr(eb, code, 3, m * 4) - eb));
            MMA_S8(acc[nt], afr[0], b0, b1);
            MMA_S8(acc[nt], afr[1], b2, b3);
        }

        __syncthreads();                      // all warps done reading E[c&1]
        if (c + 2 < NCH) {                    // prefetch E[c+2] into buf c&1
            const char* en = (const char*)g_e8 + (size_t)(c + 2) * (NC * 64);
            uint32_t sb = uE + (uint32_t)((c & 1) * 8192);
            CP_ASYNC16(sw_addr(sb, tid >> 2, tid & 3, 0), en + (uint32_t)tid * 16);
        }
        CP_COMMIT();                          // uniform group counts

        // ---- phase 1: integer max tree + quad share ----
        int cm0 = acc[0][0] > acc[0][1] ? acc[0][0] : acc[0][1];
        int cm1 = acc[0][2] > acc[0][3] ? acc[0][2] : acc[0][3];
        #pragma unroll
        for (int nt = 1; nt < 8; nt++) {
            int a0 = acc[nt][0] > acc[nt][1] ? acc[nt][0] : acc[nt][1];
            int a1 = acc[nt][2] > acc[nt][3] ? acc[nt][2] : acc[nt][3];
            cm0 = cm0 > a0 ? cm0 : a0;
            cm1 = cm1 > a1 ? cm1 : a1;
        }
        #pragma unroll
        for (int off = 1; off <= 2; off <<= 1) {
            int o0 = __shfl_xor_sync(0xffffffffu, cm0, off);
            int o1 = __shfl_xor_sync(0xffffffffu, cm1, off);
            cm0 = cm0 > o0 ? cm0 : o0;
            cm1 = cm1 > o1 ? cm1 : o1;
        }
        rmax[0] = rmax[0] > cm0 ? rmax[0] : cm0;
        rmax[1] = rmax[1] > cm1 ? rmax[1] : cm1;
        const int thr0 = rmax[0] - Mint;
        const int thr1 = rmax[1] - Mint;

        // ---- phase 2: independent predicated collection ----
        #pragma unroll
        for (int nt = 0; nt < 8; nt++) {
            const int colb = c * NC + warp_n * 64 + nt * 8 + m * 2;
            if (acc[nt][0] > thr0) { if (cnt[0] < QCAP) sp[0][cnt[0]] = colb;     cnt[0]++; }
            if (acc[nt][1] > thr0) { if (cnt[0] < QCAP) sp[0][cnt[0]] = colb + 1; cnt[0]++; }
            if (acc[nt][2] > thr1) { if (cnt[1] < QCAP) sp[1][cnt[1]] = colb;     cnt[1]++; }
            if (acc[nt][3] > thr1) { if (cnt[1] < QCAP) sp[1][cnt[1]] = colb + 1; cnt[1]++; }
        }
    }

    g_cnt[(size_t)r0 * NW + w] = cnt[0];       // raw (overflow visible)
    g_cnt[(size_t)(r0 + 8) * NW + w] = cnt[1];
}

// ---------------------------------------------------------------------------
// rescore: warp per row; slot iteration (writer = slot/QCAP), exact
// serial-FMA distance (bit-identical to R1). Overflow -> full scan.
// ---------------------------------------------------------------------------
__global__ void __launch_bounds__(256)
vq_rescore(const float* __restrict__ z, const float* __restrict__ emb) {
    __shared__ float zs[8][DIM];
    const int wid = threadIdx.x >> 5, lane = threadIdx.x & 31;
    const int row = blockIdx.x * 8 + wid;

    float2 v = ((const float2*)(z + (size_t)row * DIM))[lane];
    zs[wid][2 * lane] = v.x;
    zs[wid][2 * lane + 1] = v.y;
    __syncwarp();

    int myc = (lane < NW) ? g_cnt[(size_t)row * NW + lane] : 0;
    bool ovf = __any_sync(0xffffffffu, myc > QCAP);

    const float zzr = g_zz[row];
    const int* cbase = g_cand + (size_t)row * CAP;
    float best = __int_as_float(0x7f800000);
    int bidx = 0x7fffffff;

    if (!ovf) {
        #pragma unroll
        for (int it = 0; it < 5; it++) {      // 5*32 = 160 = CAP slots
            int slot = lane + it * 32;
            int sw = slot / QCAP;             // writer
            int j  = slot - sw * QCAP;
            int cw = __shfl_sync(0xffffffffu, myc, sw);
            if (j < cw) {
                int cand = cbase[slot];
                const float4* e4 = (const float4*)(emb + (size_t)cand * DIM);
                float s = 0.0f;
                #pragma unroll
                for (int q = 0; q < 16; q++) {
                    float4 e = __ldg(e4 + q);
                    s = __fmaf_rn(zs[wid][4 * q + 0], e.x, s);
                    s = __fmaf_rn(zs[wid][4 * q + 1], e.y, s);
                    s = __fmaf_rn(zs[wid][4 * q + 2], e.z, s);
                    s = __fmaf_rn(zs[wid][4 * q + 3], e.w, s);
                }
                float t = __fadd_rn(zzr, g_ee[cand]);
                float d = __fmaf_rn(-2.0f, s, t);
                if (d < best || (d == best && cand < bidx)) { best = d; bidx = cand; }
            }
        }
    } else {
        for (int cand = lane; cand < K_CODES; cand += 32) {
            const float4* e4 = (const float4*)(emb + (size_t)cand * DIM);
            float s = 0.0f;
            #pragma unroll
            for (int q = 0; q < 16; q++) {
                float4 e = __ldg(e4 + q);
                s = __fmaf_rn(zs[wid][4 * q + 0], e.x, s);
                s = __fmaf_rn(zs[wid][4 * q + 1], e.y, s);
                s = __fmaf_rn(zs[wid][4 * q + 2], e.z, s);
                s = __fmaf_rn(zs[wid][4 * q + 3], e.w, s);
            }
            float t = __fadd_rn(zzr, g_ee[cand]);
            float d = __fmaf_rn(-2.0f, s, t);
            if (d < best || (d == best && cand < bidx)) { best = d; bidx = cand; }
        }
    }
    #pragma unroll
    for (int off = 16; off >= 1; off >>= 1) {
        float od = __shfl_xor_sync(0xffffffffu, best, off);
        int   oi = __shfl_xor_sync(0xffffffffu, bidx, off);
        if (od < best || (od == best && oi < bidx)) { best = od; bidx = oi; }
    }
    if (lane == 0) g_idx[row] = (bidx == 0x7fffffff) ? 0 : bidx;
}

// ---------------------------------------------------------------------------
// output + loss: float4-vectorized, same rounding as R1.
// ---------------------------------------------------------------------------
__global__ void vq_output(const float* __restrict__ z, const float* __restrict__ emb,
                          float* __restrict__ out, long long outSize) {
    long long t  = (long long)blockIdx.x * blockDim.x + threadIdx.x;
    long long nd = (long long)N_ROWS * DIM;
    long long nseg = nd >> 2;
    double sq = 0.0;
    if (t < nseg) {
        int row = (int)(t >> 4);
        int seg = (int)(t & 15);
        int idx = g_idx[row];
        float4 e  = __ldg((const float4*)(emb + (size_t)idx * DIM) + seg);
        float4 zv = ((const float4*)z)[t];
        float dx = __fsub_rn(e.x, zv.x), dy = __fsub_rn(e.y, zv.y);
        float dz = __fsub_rn(e.z, zv.z), dw = __fsub_rn(e.w, zv.w);
        if (t * 4 + 3 < outSize) {
            float4 o;
            o.x = __fadd_rn(zv.x, dx); o.y = __fadd_rn(zv.y, dy);
            o.z = __fadd_rn(zv.z, dz); o.w = __fadd_rn(zv.w, dw);
            ((float4*)out)[t] = o;
        }
        sq = (double)__fmul_rn(dx, dx) + (double)__fmul_rn(dy, dy)
           + (double)__fmul_rn(dz, dz) + (double)__fmul_rn(dw, dw);
        if (t < N_ROWS && nd + t < outSize) out[nd + t] = (float)g_idx[(int)t];
    }
    #pragma unroll
    for (int off = 16; off >= 1; off >>= 1) sq += __shfl_down_sync(0xffffffffu, sq, off);
    __shared__ double wsum[8];
    int lane = threadIdx.x & 31, wid = threadIdx.x >> 5;
    if (lane == 0) wsum[wid] = sq;
    __syncthreads();
    if (threadIdx.x == 0) {
        double b = 0.0;
        #pragma unroll
        for (int w = 0; w < 8; w++) b += wsum[w];
        atomicAdd(&g_loss, b);
    }
}

__global__ void vq_finalize(float* __restrict__ out, long long outSize) {
    long long nd = (long long)N_ROWS * DIM;
    if (nd + N_ROWS < outSize) {
        float mf = (float)(g_loss / (double)nd);
        out[nd + N_ROWS] = __fmaf_rn(0.5f, mf, mf);
    }
}

// ---------------------------------------------------------------------------
extern "C" void kernel_launch(void* const* d_in, const int* in_sizes, int n_in,
                              void* d_out, int out_size) {
    const float* z   = (const float*)d_in[0];
    const float* emb = (const float*)d_in[1];
    float* out = (float*)d_out;

    const int dynSmem = 128 + MT * 64 + 2 * (NC * 64);  // ~24.7 KB
    cudaFuncSetAttribute(vq_pass1, cudaFuncAttributeMaxDynamicSharedMemorySize, dynSmem);

    vq_prep1<<<(N_ROWS + K_CODES) / 8, 256>>>(z, emb);
    vq_scale<<<1, 1>>>();
    long long nq = ((long long)(N_ROWS + K_CODES) * DIM) / 4;
    vq_prep2<<<(int)((nq + 255) / 256), 256>>>(z, emb);
    vq_pass1<<<N_ROWS / MT, 512, dynSmem>>>();
    vq_rescore<<<N_ROWS / 8, 256>>>(z, emb);
    long long nd = (long long)N_ROWS * DIM;
    long long nseg = nd >> 2;
    vq_output<<<(int)((nseg + 255) / 256), 256>>>(z, emb, out, (long long)out_size);
    vq_finalize<<<1, 1>>>(out, (long long)out_size);
}

// round 14
// speedup vs baseline: 2.4893x; 1.7821x over previous
#include <cuda_runtime.h>
#include <cstdint>

#define N_ROWS 131072
#define K_CODES 4096
#define DIM 64
#define MT 128            // rows per CTA
#define NC 128            // codes per chunk
#define NCH (K_CODES/NC)  // 32
#define QCAP 20           // per writer (8 writers/row)
#define CAP (8*QCAP)      // 160 candidate slots per row
#define NW 8

// ---------------- device scratch (no allocation allowed) ----------------
__device__ float          g_zz[N_ROWS];
__device__ float          g_ee[K_CODES];
__device__ float          g_rowA[N_ROWS];   // per-row amax(z)
__device__ float          g_rowL[N_ROWS];   // per-row L1(z)
__device__ int            g_idx[N_ROWS];
__device__ double         g_loss;
__device__ unsigned       g_amaxe_b, g_L1e_b;   // float bits, monotone
__device__ float          g_qe, g_de, g_L1e;
__device__ __align__(16) signed char g_z8[(size_t)N_ROWS * DIM];   // per-row scaled
__device__ __align__(16) signed char g_e8[(size_t)K_CODES * DIM];
__device__ int2           g_cand[(size_t)N_ROWS * CAP];            // (score, col)
__device__ int            g_cnt[(size_t)N_ROWS * NW];
__device__ int            g_rmax2[(size_t)N_ROWS * 2];             // final max per n-half
__device__ int            g_Mrow[N_ROWS];                          // per-row int margin

// ---------------- PTX helpers ----------------
#define MMA_S8(c, a, b0, b1) \
    asm volatile("mma.sync.aligned.m16n8k32.row.col.s32.s8.s8.s32 " \
        "{%0,%1,%2,%3}, {%4,%5,%6,%7}, {%8,%9}, {%0,%1,%2,%3};" \
        : "+r"((c)[0]), "+r"((c)[1]), "+r"((c)[2]), "+r"((c)[3]) \
        : "r"((a)[0]), "r"((a)[1]), "r"((a)[2]), "r"((a)[3]), "r"(b0), "r"(b1))

#define CP_ASYNC16(sa, gp) \
    asm volatile("cp.async.cg.shared.global [%0], [%1], 16;" :: "r"((uint32_t)(sa)), "l"(gp) : "memory")
#define CP_COMMIT()  asm volatile("cp.async.commit_group;" ::: "memory")
#define CP_WAITG(n)  asm volatile("cp.async.wait_group %0;" :: "n"(n) : "memory")

__device__ __forceinline__ uint32_t smem_u32(const void* p) {
    uint32_t a;
    asm("{ .reg .u64 t; cvta.to.shared.u64 t, %1; cvt.u32.u64 %0, t; }" : "=r"(a) : "l"(p));
    return a;
}
// 64B rows, 4x16B slots, slot XOR (row>>1)&3 -> conflict-free frag loads
__device__ __forceinline__ uint32_t sw_addr(uint32_t base, int row, int slot, int m4) {
    return base + (uint32_t)row * 64u + (uint32_t)((slot ^ ((row >> 1) & 3)) << 4) + (uint32_t)m4;
}

// ---------------------------------------------------------------------------
// prep1: warp per row. z rows: per-row amax/L1 + inline per-row int8
// quantization (qz_r = 127/amax_r). e rows: hierarchical global amax/L1.
// The barrier is UNCONDITIONAL; only the final atomic is branch-guarded
// (blocks are homogeneous: z-blocks are exactly [0, N_ROWS/8)).
// ---------------------------------------------------------------------------
__global__ void vq_prep1(const float* __restrict__ z, const float* __restrict__ emb) {
    __shared__ float s_am[8], s_l1[8];
    int wid = threadIdx.x >> 5, lane = threadIdx.x & 31;
    int r = blockIdx.x * 8 + wid;
    if (blockIdx.x == 0 && threadIdx.x == 0) g_loss = 0.0;
    bool isZ = (r < N_ROWS);
    const float* src = isZ ? z + (size_t)r * DIM
                           : emb + (size_t)(r - N_ROWS) * DIM;
    float2 v = ((const float2*)src)[lane];
    double s = (double)__fmul_rn(v.x, v.x) + (double)__fmul_rn(v.y, v.y);
    float l1 = fabsf(v.x) + fabsf(v.y);
    float am = fmaxf(fabsf(v.x), fabsf(v.y));
    #pragma unroll
    for (int off = 16; off; off >>= 1) {          // xor: all lanes get results
        s  += __shfl_xor_sync(0xffffffffu, s, off);
        l1 += __shfl_xor_sync(0xffffffffu, l1, off);
        am  = fmaxf(am, __shfl_xor_sync(0xffffffffu, am, off));
    }
    if (isZ) {
        float qzr = 127.0f / am;
        char2 c;
        c.x = (signed char)__float2int_rn(v.x * qzr);
        c.y = (signed char)__float2int_rn(v.y * qzr);
        ((char2*)(g_z8 + (size_t)r * DIM))[lane] = c;
        if (lane == 0) { g_zz[r] = (float)s; g_rowA[r] = am; g_rowL[r] = l1; }
    } else {
        if (lane == 0) g_ee[r - N_ROWS] = (float)s;
    }
    if (lane == 0) { s_am[wid] = am; s_l1[wid] = l1; }
    __syncthreads();                               // unconditional
    if (threadIdx.x == 0 && r >= N_ROWS) {         // e-blocks only
        float bam = s_am[0], bl1 = s_l1[0];
        #pragma unroll
        for (int i = 1; i < 8; i++) { bam = fmaxf(bam, s_am[i]); bl1 = fmaxf(bl1, s_l1[i]); }
        atomicMax(&g_amaxe_b, __float_as_uint(bam));
        atomicMax(&g_L1e_b,   __float_as_uint(bl1));
    }
}

// scale consts for e (single thread)
__global__ void vq_scale() {
    float ame = __uint_as_float(g_amaxe_b);
    float qe = 127.0f / ame;
    g_qe = qe;
    g_de = 0.5001f / qe;
    g_L1e = __uint_as_float(g_L1e_b);
}

// prep2e: quantize emb to int8 with global qe
__global__ void vq_prep2e(const float* __restrict__ emb) {
    int t = blockIdx.x * blockDim.x + threadIdx.x;
    if (t >= K_CODES * DIM / 4) return;
    float q = g_qe;
    float4 v = ((const float4*)emb)[t];
    char4 c;
    c.x = (signed char)__float2int_rn(v.x * q);
    c.y = (signed char)__float2int_rn(v.y * q);
    c.z = (signed char)__float2int_rn(v.z * q);
    c.w = (signed char)__float2int_rn(v.w * q);
    ((char4*)g_e8)[t] = c;
}

// ---------------------------------------------------------------------------
// pass 1: int8 IMMA m16n8k32, 512 threads, warp grid 8(m)x2(n). Per-row
// integer margins; stores (score,col) pairs + final row max per n-half.
// ---------------------------------------------------------------------------
extern __shared__ char sm_dyn[];

__global__ void __launch_bounds__(512, 2)
vq_pass1() {
    const int tid = threadIdx.x;
    const int lane = tid & 31;
    const int wid = tid >> 5;
    const int warp_m = wid & 7;
    const int warp_n = wid >> 3;
    const int g = lane >> 2;
    const int m = lane & 3;
    const int rowBase = blockIdx.x * MT;

    char* base = (char*)(((uintptr_t)sm_dyn + 127) & ~(uintptr_t)127);
    uint32_t uZ = smem_u32(base);          // Z: 128 x 64B
    uint32_t uE = uZ + MT * 64;            // E: 2 x (128 x 64B)

    {
        const char* zsrc = (const char*)g_z8 + (size_t)rowBase * 64;
        CP_ASYNC16(sw_addr(uZ, tid >> 2, tid & 3, 0), zsrc + (uint32_t)tid * 16);
        const char* e0 = (const char*)g_e8;
        CP_ASYNC16(sw_addr(uE, tid >> 2, tid & 3, 0), e0 + (uint32_t)tid * 16);
        CP_COMMIT();
        const char* e1 = (const char*)g_e8 + NC * 64;
        CP_ASYNC16(sw_addr(uE + 8192, tid >> 2, tid & 3, 0), e1 + (uint32_t)tid * 16);
        CP_COMMIT();
    }
    CP_WAITG(1);
    __syncthreads();

    int afr[2][4];
    {
        const int rlo = warp_m * 16 + g, rhi = rlo + 8;
        #pragma unroll
        for (int kc = 0; kc < 2; kc++) {
            afr[kc][0] = *(const int*)(base + (sw_addr(uZ, rlo, kc * 2,     m * 4) - uZ));
            afr[kc][1] = *(const int*)(base + (sw_addr(uZ, rhi, kc * 2,     m * 4) - uZ));
            afr[kc][2] = *(const int*)(base + (sw_addr(uZ, rlo, kc * 2 + 1, m * 4) - uZ));
            afr[kc][3] = *(const int*)(base + (sw_addr(uZ, rhi, kc * 2 + 1, m * 4) - uZ));
        }
    }

    const int w = warp_n * 4 + m;
    const int r0 = rowBase + warp_m * 16 + g;

    // per-row sound integer margins (conservative float math + pads)
    int Mint0, Mint1;
    {
        float qe = g_qe, de = g_de, L1e = g_L1e;
        float am0 = g_rowA[r0],     l10 = g_rowL[r0];
        float am1 = g_rowA[r0 + 8], l11 = g_rowL[r0 + 8];
        float dz0 = 0.5001f * am0 / 127.0f;
        float dz1 = 0.5001f * am1 / 127.0f;
        float Ms0 = (2.0f * (de * l10 + dz0 * L1e + 64.0f * dz0 * de)) * 1.03f + 1.2e-5f;
        float Ms1 = (2.0f * (de * l11 + dz1 * L1e + 64.0f * dz1 * de)) * 1.03f + 1.2e-5f;
        Mint0 = (int)ceilf(Ms0 * (127.0f / am0) * qe) + 2;
        Mint1 = (int)ceilf(Ms1 * (127.0f / am1) * qe) + 2;
    }

    int rmax[2] = {-(1 << 29), -(1 << 29)};
    int cnt[2] = {0, 0};
    int2* sp[2];
    sp[0] = g_cand + (size_t)r0 * CAP + w * QCAP;
    sp[1] = g_cand + (size_t)(r0 + 8) * CAP + w * QCAP;

    for (int c = 0; c < NCH; c++) {
        if (c) { CP_WAITG(1); __syncthreads(); }
        char* ebuf = base + (MT * 64) + (c & 1) * 8192;
        uint32_t eb = uE + (uint32_t)((c & 1) * 8192);

        int acc[8][4];
        #pragma unroll
        for (int nt = 0; nt < 8; nt++)
            #pragma unroll
            for (int q = 0; q < 4; q++) acc[nt][q] = 0;

        #pragma unroll
        for (int nt = 0; nt < 8; nt++) {
            const int code = warp_n * 64 + nt * 8 + g;
            int b0 = *(const int*)(ebuf + (sw_addr(eb, code, 0, m * 4) - eb));
            int b1 = *(const int*)(ebuf + (sw_addr(eb, code, 1, m * 4) - eb));
            int b2 = *(const int*)(ebuf + (sw_addr(eb, code, 2, m * 4) - eb));
            int b3 = *(const int*)(ebuf + (sw_addr(eb, code, 3, m * 4) - eb));
            MMA_S8(acc[nt], afr[0], b0, b1);
            MMA_S8(acc[nt], afr[1], b2, b3);
        }

        __syncthreads();
        if (c + 2 < NCH) {
            const char* en = (const char*)g_e8 + (size_t)(c + 2) * (NC * 64);
            uint32_t sb = uE + (uint32_t)((c & 1) * 8192);
            CP_ASYNC16(sw_addr(sb, tid >> 2, tid & 3, 0), en + (uint32_t)tid * 16);
        }
        CP_COMMIT();

        // phase 1: integer max tree + quad share
        int cm0 = acc[0][0] > acc[0][1] ? acc[0][0] : acc[0][1];
        int cm1 = acc[0][2] > acc[0][3] ? acc[0][2] : acc[0][3];
        #pragma unroll
        for (int nt = 1; nt < 8; nt++) {
            int a0 = acc[nt][0] > acc[nt][1] ? acc[nt][0] : acc[nt][1];
            int a1 = acc[nt][2] > acc[nt][3] ? acc[nt][2] : acc[nt][3];
            cm0 = cm0 > a0 ? cm0 : a0;
            cm1 = cm1 > a1 ? cm1 : a1;
        }
        #pragma unroll
        for (int off = 1; off <= 2; off <<= 1) {
            int o0 = __shfl_xor_sync(0xffffffffu, cm0, off);
            int o1 = __shfl_xor_sync(0xffffffffu, cm1, off);
            cm0 = cm0 > o0 ? cm0 : o0;
            cm1 = cm1 > o1 ? cm1 : o1;
        }
        rmax[0] = rmax[0] > cm0 ? rmax[0] : cm0;
        rmax[1] = rmax[1] > cm1 ? rmax[1] : cm1;
        const int thr0 = rmax[0] - Mint0;
        const int thr1 = rmax[1] - Mint1;

        // phase 2: collect (score, col)
        #pragma unroll
        for (int nt = 0; nt < 8; nt++) {
            const int colb = c * NC + warp_n * 64 + nt * 8 + m * 2;
            if (acc[nt][0] > thr0) { if (cnt[0] < QCAP) sp[0][cnt[0]] = make_int2(acc[nt][0], colb);     cnt[0]++; }
            if (acc[nt][1] > thr0) { if (cnt[0] < QCAP) sp[0][cnt[0]] = make_int2(acc[nt][1], colb + 1); cnt[0]++; }
            if (acc[nt][2] > thr1) { if (cnt[1] < QCAP) sp[1][cnt[1]] = make_int2(acc[nt][2], colb);     cnt[1]++; }
            if (acc[nt][3] > thr1) { if (cnt[1] < QCAP) sp[1][cnt[1]] = make_int2(acc[nt][3], colb + 1); cnt[1]++; }
        }
    }

    g_cnt[(size_t)r0 * NW + w] = cnt[0];
    g_cnt[(size_t)(r0 + 8) * NW + w] = cnt[1];
    if (m == 0) {                                   // quad-uniform values
        g_rmax2[2 * r0 + warp_n] = rmax[0];
        g_rmax2[2 * (r0 + 8) + warp_n] = rmax[1];
        if (warp_n == 0) { g_Mrow[r0] = Mint0; g_Mrow[r0 + 8] = Mint1; }
    }
}

// ---------------------------------------------------------------------------
// rescore: warp per row (R11-proven skeleton) + re-filter of stored
// (score,col) pairs against FINAL row max - Mint before any exact dot.
// Exact serial-FMA distance (bit-identical to R1). Overflow -> full scan.
// ---------------------------------------------------------------------------
__global__ void __launch_bounds__(256)
vq_rescore(const float* __restrict__ z, const float* __restrict__ emb) {
    __shared__ float zs[8][DIM];
    const int wid = threadIdx.x >> 5, lane = threadIdx.x & 31;
    const int row = blockIdx.x * 8 + wid;

    float2 v = ((const float2*)(z + (size_t)row * DIM))[lane];
    zs[wid][2 * lane] = v.x;
    zs[wid][2 * lane + 1] = v.y;
    __syncwarp();

    int myc = (lane < NW) ? g_cnt[(size_t)row * NW + lane] : 0;
    bool ovf = __any_sync(0xffffffffu, myc > QCAP);

    const float zzr = g_zz[row];
    float best = __int_as_float(0x7f800000);
    int bidx = 0x7fffffff;

    if (!ovf) {
        int Mint = g_rmax2[0] * 0 + g_Mrow[row];   // plain load (kept simple)
        int f0 = g_rmax2[2 * row], f1 = g_rmax2[2 * row + 1];
        int thr = (f0 > f1 ? f0 : f1) - Mint;
        const int2* cb = g_cand + (size_t)row * CAP;
        #pragma unroll
        for (int it = 0; it < 5; it++) {           // 5*32 = 160 = CAP slots
            int slot = lane + it * 32;
            int sw = slot / QCAP;                  // writer
            int j  = slot - sw * QCAP;
            int cw = __shfl_sync(0xffffffffu, myc, sw);
            if (j < cw) {
                int2 e = cb[slot];
                if (e.x > thr) {                   // survived final-max refilter
                    int cand = e.y;
                    const float4* e4 = (const float4*)(emb + (size_t)cand * DIM);
                    float s = 0.0f;
                    #pragma unroll
                    for (int q = 0; q < 16; q++) {
                        float4 ev = __ldg(e4 + q);
                        s = __fmaf_rn(zs[wid][4 * q + 0], ev.x, s);
                        s = __fmaf_rn(zs[wid][4 * q + 1], ev.y, s);
                        s = __fmaf_rn(zs[wid][4 * q + 2], ev.z, s);
                        s = __fmaf_rn(zs[wid][4 * q + 3], ev.w, s);
                    }
                    float t = __fadd_rn(zzr, g_ee[cand]);
                    float d = __fmaf_rn(-2.0f, s, t);
                    if (d < best || (d == best && cand < bidx)) { best = d; bidx = cand; }
                }
            }
        }
    } else {
        for (int cand = lane; cand < K_CODES; cand += 32) {
            const float4* e4 = (const float4*)(emb + (size_t)cand * DIM);
            float s = 0.0f;
            #pragma unroll
            for (int q = 0; q < 16; q++) {
                float4 ev = __ldg(e4 + q);
                s = __fmaf_rn(zs[wid][4 * q + 0], ev.x, s);
                s = __fmaf_rn(zs[wid][4 * q + 1], ev.y, s);
                s = __fmaf_rn(zs[wid][4 * q + 2], ev.z, s);
                s = __fmaf_rn(zs[wid][4 * q + 3], ev.w, s);
            }
            float t = __fadd_rn(zzr, g_ee[cand]);
            float d = __fmaf_rn(-2.0f, s, t);
            if (d < best || (d == best && cand < bidx)) { best = d; bidx = cand; }
        }
    }
    #pragma unroll
    for (int off = 16; off >= 1; off >>= 1) {
        float od = __shfl_xor_sync(0xffffffffu, best, off);
        int   oi = __shfl_xor_sync(0xffffffffu, bidx, off);
        if (od < best || (od == best && oi < bidx)) { best = od; bidx = oi; }
    }
    if (lane == 0) g_idx[row] = (bidx == 0x7fffffff) ? 0 : bidx;
}

// ---------------------------------------------------------------------------
// output + loss: float4-vectorized, same rounding as R1.
// ---------------------------------------------------------------------------
__global__ void vq_output(const float* __restrict__ z, const float* __restrict__ emb,
                          float* __restrict__ out, long long outSize) {
    long long t  = (long long)blockIdx.x * blockDim.x + threadIdx.x;
    long long nd = (long long)N_ROWS * DIM;
    long long nseg = nd >> 2;
    double sq = 0.0;
    if (t < nseg) {
        int row = (int)(t >> 4);
        int seg = (int)(t & 15);
        int idx = g_idx[row];
        float4 e  = __ldg((const float4*)(emb + (size_t)idx * DIM) + seg);
        float4 zv = ((const float4*)z)[t];
        float dx = __fsub_rn(e.x, zv.x), dy = __fsub_rn(e.y, zv.y);
        float dz = __fsub_rn(e.z, zv.z), dw = __fsub_rn(e.w, zv.w);
        if (t * 4 + 3 < outSize) {
            float4 o;
            o.x = __fadd_rn(zv.x, dx); o.y = __fadd_rn(zv.y, dy);
            o.z = __fadd_rn(zv.z, dz); o.w = __fadd_rn(zv.w, dw);
            ((float4*)out)[t] = o;
        }
        sq = (double)__fmul_rn(dx, dx) + (double)__fmul_rn(dy, dy)
           + (double)__fmul_rn(dz, dz) + (double)__fmul_rn(dw, dw);
        if (t < N_ROWS && nd + t < outSize) out[nd + t] = (float)g_idx[(int)t];
    }
    #pragma unroll
    for (int off = 16; off >= 1; off >>= 1) sq += __shfl_down_sync(0xffffffffu, sq, off);
    __shared__ double wsum[8];
    int lane = threadIdx.x & 31, wid = threadIdx.x >> 5;
    if (lane == 0) wsum[wid] = sq;
    __syncthreads();
    if (threadIdx.x == 0) {
        double b = 0.0;
        #pragma unroll
        for (int w = 0; w < 8; w++) b += wsum[w];
        atomicAdd(&g_loss, b);
    }
}

__global__ void vq_finalize(float* __restrict__ out, long long outSize) {
    long long nd = (long long)N_ROWS * DIM;
    if (nd + N_ROWS < outSize) {
        float mf = (float)(g_loss / (double)nd);
        out[nd + N_ROWS] = __fmaf_rn(0.5f, mf, mf);
    }
}

// ---------------------------------------------------------------------------
extern "C" void kernel_launch(void* const* d_in, const int* in_sizes, int n_in,
                              void* d_out, int out_size) {
    const float* z   = (const float*)d_in[0];
    const float* emb = (const float*)d_in[1];
    float* out = (float*)d_out;

    const int dynSmem = 128 + MT * 64 + 2 * (NC * 64);  // ~24.7 KB
    cudaFuncSetAttribute(vq_pass1, cudaFuncAttributeMaxDynamicSharedMemorySize, dynSmem);

    vq_prep1<<<(N_ROWS + K_CODES) / 8, 256>>>(z, emb);
    vq_scale<<<1, 1>>>();
    vq_prep2e<<<(K_CODES * DIM / 4 + 255) / 256, 256>>>(emb);
    vq_pass1<<<N_ROWS / MT, 512, dynSmem>>>();
    vq_rescore<<<N_ROWS / 8, 256>>>(z, emb);
    long long nd = (long long)N_ROWS * DIM;
    long long nseg = nd >> 2;
    vq_output<<<(int)((nseg + 255) / 256), 256>>>(z, emb, out, (long long)out_size);
    vq_finalize<<<1, 1>>>(out, (long long)out_size);
}

// round 17
// speedup vs baseline: 2.5792x; 1.0361x over previous
#include <cuda_runtime.h>
#include <cstdint>

#define N_ROWS 131072
#define K_CODES 4096
#define DIM 64
#define MT 128            // rows per CTA
#define NC 128            // codes per chunk
#define NCH (K_CODES/NC)  // 32
#define QCAP 20           // per writer (8 writers/row)
#define CAP (8*QCAP)      // 160 candidate slots per row
#define NW 8

// ---------------- device scratch (no allocation allowed) ----------------
__device__ float          g_zz[N_ROWS];
__device__ float          g_ee[K_CODES];
__device__ float          g_rowA[N_ROWS];   // per-row amax(z)
__device__ float          g_rowL[N_ROWS];   // per-row L1(z)
__device__ int            g_idx[N_ROWS];
__device__ double         g_loss;
__device__ unsigned       g_amaxe_b, g_L1e_b;   // float bits, monotone
__device__ float          g_qe, g_de, g_L1e;
__device__ __align__(16) signed char g_z8[(size_t)N_ROWS * DIM];   // per-row scaled
__device__ __align__(16) signed char g_e8[(size_t)K_CODES * DIM];
__device__ int2           g_cand[(size_t)N_ROWS * CAP];            // (score, col)
__device__ int            g_cnt[(size_t)N_ROWS * NW];
__device__ int            g_rmax2[(size_t)N_ROWS * 2];             // final max per n-half
__device__ int            g_Mrow[N_ROWS];                          // per-row int margin

// ---------------- PTX helpers ----------------
#define MMA_S8(c, a, b0, b1) \
    asm volatile("mma.sync.aligned.m16n8k32.row.col.s32.s8.s8.s32 " \
        "{%0,%1,%2,%3}, {%4,%5,%6,%7}, {%8,%9}, {%0,%1,%2,%3};" \
        : "+r"((c)[0]), "+r"((c)[1]), "+r"((c)[2]), "+r"((c)[3]) \
        : "r"((a)[0]), "r"((a)[1]), "r"((a)[2]), "r"((a)[3]), "r"(b0), "r"(b1))

#define LDMATRIX_X4(r, a) \
    asm volatile("ldmatrix.sync.aligned.m8n8.x4.shared.b16 {%0,%1,%2,%3}, [%4];" \
        : "=r"((r)[0]), "=r"((r)[1]), "=r"((r)[2]), "=r"((r)[3]) : "r"(a))

#define CP_ASYNC16(sa, gp) \
    asm volatile("cp.async.cg.shared.global [%0], [%1], 16;" :: "r"((uint32_t)(sa)), "l"(gp) : "memory")
#define CP_COMMIT()  asm volatile("cp.async.commit_group;" ::: "memory")
#define CP_WAITG(n)  asm volatile("cp.async.wait_group %0;" :: "n"(n) : "memory")

__device__ __forceinline__ uint32_t smem_u32(const void* p) {
    uint32_t a;
    asm("{ .reg .u64 t; cvta.to.shared.u64 t, %1; cvt.u32.u64 %0, t; }" : "=r"(a) : "l"(p));
    return a;
}
// 64B rows, 4x16B slots, slot XOR (row>>1)&3 -> conflict-free frag loads
__device__ __forceinline__ uint32_t sw_addr(uint32_t base, int row, int slot, int m4) {
    return base + (uint32_t)row * 64u + (uint32_t)((slot ^ ((row >> 1) & 3)) << 4) + (uint32_t)m4;
}

// ---------------------------------------------------------------------------
// prep1: warp per row. z rows: per-row amax/L1 + inline per-row int8
// quantization (qz_r = 127/amax_r). e rows: hierarchical global amax/L1.
// Barrier unconditional; final atomic branch-guarded (blocks homogeneous).
// ---------------------------------------------------------------------------
__global__ void vq_prep1(const float* __restrict__ z, const float* __restrict__ emb) {
    __shared__ float s_am[8], s_l1[8];
    int wid = threadIdx.x >> 5, lane = threadIdx.x & 31;
    int r = blockIdx.x * 8 + wid;
    if (blockIdx.x == 0 && threadIdx.x == 0) g_loss = 0.0;
    bool isZ = (r < N_ROWS);
    const float* src = isZ ? z + (size_t)r * DIM
                           : emb + (size_t)(r - N_ROWS) * DIM;
    float2 v = ((const float2*)src)[lane];
    double s = (double)__fmul_rn(v.x, v.x) + (double)__fmul_rn(v.y, v.y);
    float l1 = fabsf(v.x) + fabsf(v.y);
    float am = fmaxf(fabsf(v.x), fabsf(v.y));
    #pragma unroll
    for (int off = 16; off; off >>= 1) {          // xor: all lanes get results
        s  += __shfl_xor_sync(0xffffffffu, s, off);
        l1 += __shfl_xor_sync(0xffffffffu, l1, off);
        am  = fmaxf(am, __shfl_xor_sync(0xffffffffu, am, off));
    }
    if (isZ) {
        float qzr = 127.0f / am;
        char2 c;
        c.x = (signed char)__float2int_rn(v.x * qzr);
        c.y = (signed char)__float2int_rn(v.y * qzr);
        ((char2*)(g_z8 + (size_t)r * DIM))[lane] = c;
        if (lane == 0) { g_zz[r] = (float)s; g_rowA[r] = am; g_rowL[r] = l1; }
    } else {
        if (lane == 0) g_ee[r - N_ROWS] = (float)s;
    }
    if (lane == 0) { s_am[wid] = am; s_l1[wid] = l1; }
    __syncthreads();                               // unconditional
    if (threadIdx.x == 0 && r >= N_ROWS) {         // e-blocks only
        float bam = s_am[0], bl1 = s_l1[0];
        #pragma unroll
        for (int i = 1; i < 8; i++) { bam = fmaxf(bam, s_am[i]); bl1 = fmaxf(bl1, s_l1[i]); }
        atomicMax(&g_amaxe_b, __float_as_uint(bam));
        atomicMax(&g_L1e_b,   __float_as_uint(bl1));
    }
}

// scale consts for e (single thread)
__global__ void vq_scale() {
    float ame = __uint_as_float(g_amaxe_b);
    float qe = 127.0f / ame;
    g_qe = qe;
    g_de = 0.5001f / qe;
    g_L1e = __uint_as_float(g_L1e_b);
}

// prep2e: quantize emb to int8 with global qe
__global__ void vq_prep2e(const float* __restrict__ emb) {
    int t = blockIdx.x * blockDim.x + threadIdx.x;
    if (t >= K_CODES * DIM / 4) return;
    float q = g_qe;
    float4 v = ((const float4*)emb)[t];
    char4 c;
    c.x = (signed char)__float2int_rn(v.x * q);
    c.y = (signed char)__float2int_rn(v.y * q);
    c.z = (signed char)__float2int_rn(v.z * q);
    c.w = (signed char)__float2int_rn(v.w * q);
    ((char4*)g_e8)[t] = c;
}

// ---------------------------------------------------------------------------
// pass 1: int8 IMMA m16n8k32, 512 threads, warp grid 8(m)x2(n).
// R17: ldmatrix.x4 fragment loads (the ONE change vs the proven R14);
// E pipeline is R14's exact double-buffer / two-barrier structure.
// Per-row integer margins; stores (score,col) pairs + final row max.
// ---------------------------------------------------------------------------
extern __shared__ char sm_dyn[];

__global__ void __launch_bounds__(512, 2)
vq_pass1() {
    const int tid = threadIdx.x;
    const int lane = tid & 31;
    const int wid = tid >> 5;
    const int warp_m = wid & 7;
    const int warp_n = wid >> 3;
    const int g = lane >> 2;
    const int m = lane & 3;
    const int rowBase = blockIdx.x * MT;

    char* base = (char*)(((uintptr_t)sm_dyn + 127) & ~(uintptr_t)127);
    uint32_t uZ = smem_u32(base);          // Z: 128 x 64B
    uint32_t uE = uZ + MT * 64;            // E: 2 x (128 x 64B)

    // prologue: Z + E0 (group 0), E1 (group 1); swizzled 16B stores
    {
        const char* zsrc = (const char*)g_z8 + (size_t)rowBase * 64;
        CP_ASYNC16(sw_addr(uZ, tid >> 2, tid & 3, 0), zsrc + (uint32_t)tid * 16);
        const char* e0 = (const char*)g_e8;
        CP_ASYNC16(sw_addr(uE, tid >> 2, tid & 3, 0), e0 + (uint32_t)tid * 16);
        CP_COMMIT();
        const char* e1 = (const char*)g_e8 + NC * 64;
        CP_ASYNC16(sw_addr(uE + 8192, tid >> 2, tid & 3, 0), e1 + (uint32_t)tid * 16);
        CP_COMMIT();
    }
    CP_WAITG(1);
    __syncthreads();

    // A fragments via ldmatrix.x4: matrix j <- addr from lanes 8j..8j+7.
    int afr[2][4];
    {
        const int arow = warp_m * 16 + (lane & 7) + ((lane >> 3) & 1) * 8;
        #pragma unroll
        for (int kc = 0; kc < 2; kc++) {
            uint32_t addr = sw_addr(uZ, arow, kc * 2 + (lane >> 4), 0);
            LDMATRIX_X4(afr[kc], addr);
        }
    }

    const int w = warp_n * 4 + m;
    const int r0 = rowBase + warp_m * 16 + g;

    // per-row sound integer margins (conservative float math + pads)
    int Mint0, Mint1;
    {
        float qe = g_qe, de = g_de, L1e = g_L1e;
        float am0 = g_rowA[r0],     l10 = g_rowL[r0];
        float am1 = g_rowA[r0 + 8], l11 = g_rowL[r0 + 8];
        float dz0 = 0.5001f * am0 / 127.0f;
        float dz1 = 0.5001f * am1 / 127.0f;
        float Ms0 = (2.0f * (de * l10 + dz0 * L1e + 64.0f * dz0 * de)) * 1.03f + 1.2e-5f;
        float Ms1 = (2.0f * (de * l11 + dz1 * L1e + 64.0f * dz1 * de)) * 1.03f + 1.2e-5f;
        Mint0 = (int)ceilf(Ms0 * (127.0f / am0) * qe) + 2;
        Mint1 = (int)ceilf(Ms1 * (127.0f / am1) * qe) + 2;
    }

    int rmax[2] = {-(1 << 29), -(1 << 29)};
    int cnt[2] = {0, 0};
    int2* sp[2];
    sp[0] = g_cand + (size_t)r0 * CAP + w * QCAP;
    sp[1] = g_cand + (size_t)(r0 + 8) * CAP + w * QCAP;

    const int brow = warp_n * 64 + (lane & 7);    // ldmatrix row within nt stride
    const int bslot = lane >> 3;                  // matrix index 0..3 -> k slot

    for (int c = 0; c < NCH; c++) {
        if (c) { CP_WAITG(1); __syncthreads(); }
        uint32_t eb = uE + (uint32_t)((c & 1) * 8192);

        int acc[8][4];
        #pragma unroll
        for (int nt = 0; nt < 8; nt++)
            #pragma unroll
            for (int q = 0; q < 4; q++) acc[nt][q] = 0;

        #pragma unroll
        for (int nt = 0; nt < 8; nt++) {
            int bfr[4];
            uint32_t addr = sw_addr(eb, brow + nt * 8, bslot, 0);
            LDMATRIX_X4(bfr, addr);               // matrix j = k-bytes [16j,16j+16)
            MMA_S8(acc[nt], afr[0], bfr[0], bfr[1]);
            MMA_S8(acc[nt], afr[1], bfr[2], bfr[3]);
        }

        __syncthreads();                          // all warps done reading E[c&1]
        if (c + 2 < NCH) {                        // prefetch E[c+2] into buf c&1
            const char* en = (const char*)g_e8 + (size_t)(c + 2) * (NC * 64);
            uint32_t sb = uE + (uint32_t)((c & 1) * 8192);
            CP_ASYNC16(sw_addr(sb, tid >> 2, tid & 3, 0), en + (uint32_t)tid * 16);
        }
        CP_COMMIT();                              // uniform group counts

        // phase 1: integer max tree + quad share
        int cm0 = acc[0][0] > acc[0][1] ? acc[0][0] : acc[0][1];
        int cm1 = acc[0][2] > acc[0][3] ? acc[0][2] : acc[0][3];
        #pragma unroll
        for (int nt = 1; nt < 8; nt++) {
            int a0 = acc[nt][0] > acc[nt][1] ? acc[nt][0] : acc[nt][1];
            int a1 = acc[nt][2] > acc[nt][3] ? acc[nt][2] : acc[nt][3];
            cm0 = cm0 > a0 ? cm0 : a0;
            cm1 = cm1 > a1 ? cm1 : a1;
        }
        #pragma unroll
        for (int off = 1; off <= 2; off <<= 1) {
            int o0 = __shfl_xor_sync(0xffffffffu, cm0, off);
            int o1 = __shfl_xor_sync(0xffffffffu, cm1, off);
            cm0 = cm0 > o0 ? cm0 : o0;
            cm1 = cm1 > o1 ? cm1 : o1;
        }
        rmax[0] = rmax[0] > cm0 ? rmax[0] : cm0;
        rmax[1] = rmax[1] > cm1 ? rmax[1] : cm1;
        const int thr0 = rmax[0] - Mint0;
        const int thr1 = rmax[1] - Mint1;

        // phase 2: collect (score, col)
        #pragma unroll
        for (int nt = 0; nt < 8; nt++) {
            const int colb = c * NC + warp_n * 64 + nt * 8 + m * 2;
            if (acc[nt][0] > thr0) { if (cnt[0] < QCAP) sp[0][cnt[0]] = make_int2(acc[nt][0], colb);     cnt[0]++; }
            if (acc[nt][1] > thr0) { if (cnt[0] < QCAP) sp[0][cnt[0]] = make_int2(acc[nt][1], colb + 1); cnt[0]++; }
            if (acc[nt][2] > thr1) { if (cnt[1] < QCAP) sp[1][cnt[1]] = make_int2(acc[nt][2], colb);     cnt[1]++; }
            if (acc[nt][3] > thr1) { if (cnt[1] < QCAP) sp[1][cnt[1]] = make_int2(acc[nt][3], colb + 1); cnt[1]++; }
        }
    }

    g_cnt[(size_t)r0 * NW + w] = cnt[0];
    g_cnt[(size_t)(r0 + 8) * NW + w] = cnt[1];
    if (m == 0) {                                   // quad-uniform values
        g_rmax2[2 * r0 + warp_n] = rmax[0];
        g_rmax2[2 * (r0 + 8) + warp_n] = rmax[1];
        if (warp_n == 0) { g_Mrow[r0] = Mint0; g_Mrow[r0 + 8] = Mint1; }
    }
}

// ---------------------------------------------------------------------------
// rescore: warp per row; re-filter stored (score,col) pairs against FINAL
// row max - Mint, exact serial-FMA distance on survivors (bit-identical to
// R1). Overflow -> full scan.
// ---------------------------------------------------------------------------
__global__ void __launch_bounds__(256)
vq_rescore(const float* __restrict__ z, const float* __restrict__ emb) {
    __shared__ float zs[8][DIM];
    const int wid = threadIdx.x >> 5, lane = threadIdx.x & 31;
    const int row = blockIdx.x * 8 + wid;

    float2 v = ((const float2*)(z + (size_t)row * DIM))[lane];
    zs[wid][2 * lane] = v.x;
    zs[wid][2 * lane + 1] = v.y;
    __syncwarp();

    int myc = (lane < NW) ? g_cnt[(size_t)row * NW + lane] : 0;
    bool ovf = __any_sync(0xffffffffu, myc > QCAP);

    const float zzr = g_zz[row];
    float best = __int_as_float(0x7f800000);
    int bidx = 0x7fffffff;

    if (!ovf) {
        int Mint = g_Mrow[row];
        int f0 = g_rmax2[2 * row], f1 = g_rmax2[2 * row + 1];
        int thr = (f0 > f1 ? f0 : f1) - Mint;
        const int2* cb = g_cand + (size_t)row * CAP;
        #pragma unroll
        for (int it = 0; it < 5; it++) {           // 5*32 = 160 = CAP slots
            int slot = lane + it * 32;
            int sw = slot / QCAP;                  // writer
            int j  = slot - sw * QCAP;
            int cw = __shfl_sync(0xffffffffu, myc, sw);
            if (j < cw) {
                int2 e = cb[slot];
                if (e.x > thr) {                   // survived final-max refilter
                    int cand = e.y;
                    const float4* e4 = (const float4*)(emb + (size_t)cand * DIM);
                    float s = 0.0f;
                    #pragma unroll
                    for (int q = 0; q < 16; q++) {
                        float4 ev = __ldg(e4 + q);
                        s = __fmaf_rn(zs[wid][4 * q + 0], ev.x, s);
                        s = __fmaf_rn(zs[wid][4 * q + 1], ev.y, s);
                        s = __fmaf_rn(zs[wid][4 * q + 2], ev.z, s);
                        s = __fmaf_rn(zs[wid][4 * q + 3], ev.w, s);
                    }
                    float t = __fadd_rn(zzr, g_ee[cand]);
                    float d = __fmaf_rn(-2.0f, s, t);
                    if (d < best || (d == best && cand < bidx)) { best = d; bidx = cand; }
                }
            }
        }
    } else {
        for (int cand = lane; cand < K_CODES; cand += 32) {
            const float4* e4 = (const float4*)(emb + (size_t)cand * DIM);
            float s = 0.0f;
            #pragma unroll
            for (int q = 0; q < 16; q++) {
                float4 ev = __ldg(e4 + q);
                s = __fmaf_rn(zs[wid][4 * q + 0], ev.x, s);
                s = __fmaf_rn(zs[wid][4 * q + 1], ev.y, s);
                s = __fmaf_rn(zs[wid][4 * q + 2], ev.z, s);
                s = __fmaf_rn(zs[wid][4 * q + 3], ev.w, s);
            }
            float t = __fadd_rn(zzr, g_ee[cand]);
            float d = __fmaf_rn(-2.0f, s, t);
            if (d < best || (d == best && cand < bidx)) { best = d; bidx = cand; }
        }
    }
    #pragma unroll
    for (int off = 16; off >= 1; off >>= 1) {
        float od = __shfl_xor_sync(0xffffffffu, best, off);
        int   oi = __shfl_xor_sync(0xffffffffu, bidx, off);
        if (od < best || (od == best && oi < bidx)) { best = od; bidx = oi; }
    }
    if (lane == 0) g_idx[row] = (bidx == 0x7fffffff) ? 0 : bidx;
}

// ---------------------------------------------------------------------------
// output + loss: float4-vectorized, same rounding as R1.
// ---------------------------------------------------------------------------
__global__ void vq_output(const float* __restrict__ z, const float* __restrict__ emb,
                          float* __restrict__ out, long long outSize) {
    long long t  = (long long)blockIdx.x * blockDim.x + threadIdx.x;
    long long nd = (long long)N_ROWS * DIM;
    long long nseg = nd >> 2;
    double sq = 0.0;
    if (t < nseg) {
        int row = (int)(t >> 4);
        int seg = (int)(t & 15);
        int idx = g_idx[row];
        float4 e  = __ldg((const float4*)(emb + (size_t)idx * DIM) + seg);
        float4 zv = ((const float4*)z)[t];
        float dx = __fsub_rn(e.x, zv.x), dy = __fsub_rn(e.y, zv.y);
        float dz = __fsub_rn(e.z, zv.z), dw = __fsub_rn(e.w, zv.w);
        if (t * 4 + 3 < outSize) {
            float4 o;
            o.x = __fadd_rn(zv.x, dx); o.y = __fadd_rn(zv.y, dy);
            o.z = __fadd_rn(zv.z, dz); o.w = __fadd_rn(zv.w, dw);
            ((float4*)out)[t] = o;
        }
        sq = (double)__fmul_rn(dx, dx) + (double)__fmul_rn(dy, dy)
           + (double)__fmul_rn(dz, dz) + (double)__fmul_rn(dw, dw);
        if (t < N_ROWS && nd + t < outSize) out[nd + t] = (float)g_idx[(int)t];
    }
    #pragma unroll
    for (int off = 16; off >= 1; off >>= 1) sq += __shfl_down_sync(0xffffffffu, sq, off);
    __shared__ double wsum[8];
    int lane = threadIdx.x & 31, wid = threadIdx.x >> 5;
    if (lane == 0) wsum[wid] = sq;
    __syncthreads();
    if (threadIdx.x == 0) {
        double b = 0.0;
        #pragma unroll
        for (int w = 0; w < 8; w++) b += wsum[w];
        atomicAdd(&g_loss, b);
    }
}

__global__ void vq_finalize(float* __restrict__ out, long long outSize) {
    long long nd = (long long)N_ROWS * DIM;
    if (nd + N_ROWS < outSize) {
        float mf = (float)(g_loss / (double)nd);
        out[nd + N_ROWS] = __fmaf_rn(0.5f, mf, mf);
    }
}

// ---------------------------------------------------------------------------
extern "C" void kernel_launch(void* const* d_in, const int* in_sizes, int n_in,
                              void* d_out, int out_size) {
    const float* z   = (const float*)d_in[0];
    const float* emb = (const float*)d_in[1];
    float* out = (float*)d_out;

    const int dynSmem = 128 + MT * 64 + 2 * (NC * 64);  // ~24.7 KB (R14 layout)
    cudaFuncSetAttribute(vq_pass1, cudaFuncAttributeMaxDynamicSharedMemorySize, dynSmem);

    vq_prep1<<<(N_ROWS + K_CODES) / 8, 256>>>(z, emb);
    vq_scale<<<1, 1>>>();
    vq_prep2e<<<(K_CODES * DIM / 4 + 255) / 256, 256>>>(emb);
    vq_pass1<<<N_ROWS / MT, 512, dynSmem>>>();
    vq_rescore<<<N_ROWS / 8, 256>>>(z, emb);
    long long nd = (long long)N_ROWS * DIM;
    long long nseg = nd >> 2;
    vq_output<<<(int)((nseg + 255) / 256), 256>>>(z, emb, out, (long long)out_size);
    vq_finalize<<<1, 1>>>(out, (long long)out_size);
}